// round 13
// baseline (speedup 1.0000x reference)
#include <cuda_runtime.h>
#include <math.h>

// Problem constants
#define B_   8
#define LQ_  512
#define T_   8192
#define DIM_ 256
#define H_   8
#define HD_  32

// ---------------------------------------------------------------------------
// Scratch (device globals: allocation-free per harness rules)
// ---------------------------------------------------------------------------
__device__ float g_Q[(size_t)B_ * LQ_ * DIM_];              //  4 MB, [b][q][256]
__device__ float g_K[(size_t)B_ * H_ * HD_ * T_];           // 64 MB, TRANSPOSED [b][h][d][t]
__device__ float g_V[(size_t)B_ * H_ * T_ * HD_];           // 64 MB, [b][h][t][d]
__device__ float g_mask[(size_t)LQ_ * T_];                  // 16 MB, [q][t]
__device__ float g_att[(size_t)B_ * LQ_ * DIM_];            //  4 MB, [b][q][h*32+d]

// ---------------------------------------------------------------------------
// f32x2 packed helpers (Blackwell): 2 fp32 ops per instruction, exact fp32.
// ---------------------------------------------------------------------------
__device__ __forceinline__ unsigned long long dup2(float x) {
    unsigned long long r;
    asm("mov.b64 %0, {%1, %1};" : "=l"(r) : "f"(x));
    return r;
}
__device__ __forceinline__ unsigned long long pack2(float lo, float hi) {
    unsigned long long r;
    asm("mov.b64 %0, {%1, %2};" : "=l"(r) : "f"(lo), "f"(hi));
    return r;
}
__device__ __forceinline__ void unpack2(float& lo, float& hi, unsigned long long v) {
    asm("mov.b64 {%0, %1}, %2;" : "=f"(lo), "=f"(hi) : "l"(v));
}
__device__ __forceinline__ void ffma2(unsigned long long& acc,
                                      unsigned long long a, unsigned long long b) {
    asm("fma.rn.f32x2 %0, %1, %2, %0;" : "+l"(acc) : "l"(a), "l"(b));
}
__device__ __forceinline__ void fmul2(unsigned long long& acc, unsigned long long a) {
    asm("mul.rn.f32x2 %0, %0, %1;" : "+l"(acc) : "l"(a));
}
__device__ __forceinline__ unsigned long long fadd2(unsigned long long a,
                                                    unsigned long long b) {
    unsigned long long r;
    asm("add.rn.f32x2 %0, %1, %2;" : "=l"(r) : "l"(a), "l"(b));
    return r;
}

// ---------------------------------------------------------------------------
// Mask precompute (unchanged math; exact same values as R8)
// ---------------------------------------------------------------------------
__global__ void mask_kernel(const float* __restrict__ rel_bias,
                            const float* __restrict__ mask_scale)
{
    int idx = blockIdx.x * 256 + threadIdx.x;
    int q = idx >> 13;
    int t = idx & (T_ - 1);
    const float step = 8191.0f / 511.0f;
    float tau = (float)q * step;
    float dt = (float)t - tau;
    float dtc = fminf(fmaxf(dt, -128.0f), 128.0f);
    int bi = (int)dtc + 128;
    float bias = rel_bias[bi];
    float z = dt * (1.0f / 64.0f);
    float lg = logf(expf(-0.5f * z * z) + 1e-6f);
    g_mask[idx] = mask_scale[0] * (bias + lg);
}

// ---------------------------------------------------------------------------
// Resident-W GEMM:  C[m][n] = sum_k A[m][k] * Wt[n][k] + bias,  Kdim = 256
// CTA tile 128m x 64n, 256 threads (tx = n-group of 4, ty = m-group of 8).
// Wt slice (64 x 256) loaded ONCE into smem Ws[k][n] (row stride 68 floats).
// A chunks (128 x 16) double-buffered as dup-f32x2 Ad[k][m] (stride 130 ulong),
// register-prefetched one chunk ahead; ONE barrier per chunk.
// mode 0: row-major C0 (ld = 256)
// mode 1: V head-major: m = token, n = h*32+d
// mode 2: K transposed: m = output dim (bias per ROW), n = token -> [b][h][d][t]
// Dynamic smem: 256*68*4 + 2*16*130*8 = 69632 + 33280 = 102912 B (2 CTAs/SM).
// ---------------------------------------------------------------------------
#define GEMM_SMEM (256 * 68 * 4 + 2 * 16 * 130 * 8)

__global__ __launch_bounds__(256, 2) void gemm_rw(
    const float* __restrict__ A, const float* __restrict__ Wt,
    const float* __restrict__ bias, float* __restrict__ C0, int mode)
{
    extern __shared__ char smraw[];
    float* Ws = (float*)smraw;                                     // [256][68]
    unsigned long long* Ad = (unsigned long long*)(smraw + 256 * 68 * 4);

    const int tid = threadIdx.x;
    const int tx = tid & 15;          // n group (4 cols)
    const int ty = tid >> 4;          // m group (8 rows)
    const int n0 = blockIdx.x << 6;
    const int m0 = blockIdx.y << 7;

    // ---- resident W: lane-major over n rows -> conflict-free STS ----
#pragma unroll
    for (int it = 0; it < 16; it++) {
        int i = tid + it * 256;           // 0..4095
        int r  = i & 63;                  // n row within tile
        int c4 = i >> 6;                  // k float4 group 0..63
        float4 v = *(const float4*)(Wt + (size_t)(n0 + r) * 256 + c4 * 4);
        Ws[(4 * c4 + 0) * 68 + r] = v.x;
        Ws[(4 * c4 + 1) * 68 + r] = v.y;
        Ws[(4 * c4 + 2) * 68 + r] = v.z;
        Ws[(4 * c4 + 3) * 68 + r] = v.w;
    }

    unsigned long long acc[8][2];
#pragma unroll
    for (int i = 0; i < 8; i++) { acc[i][0] = 0ull; acc[i][1] = 0ull; }

    const int lm = tid >> 1;              // m row 0..127
    const int lh = (tid & 1) << 3;        // k offset 0 or 8

    // prefetch chunk 0
    float4 a0 = *(const float4*)(A + (size_t)(m0 + lm) * 256 + lh);
    float4 a1 = *(const float4*)(A + (size_t)(m0 + lm) * 256 + lh + 4);

    int buf = 0;
    for (int kc = 0; kc < 256; kc += 16) {
        unsigned long long* ad = Ad + buf * (16 * 130);
        ad[(lh + 0) * 130 + lm] = dup2(a0.x);
        ad[(lh + 1) * 130 + lm] = dup2(a0.y);
        ad[(lh + 2) * 130 + lm] = dup2(a0.z);
        ad[(lh + 3) * 130 + lm] = dup2(a0.w);
        ad[(lh + 4) * 130 + lm] = dup2(a1.x);
        ad[(lh + 5) * 130 + lm] = dup2(a1.y);
        ad[(lh + 6) * 130 + lm] = dup2(a1.z);
        ad[(lh + 7) * 130 + lm] = dup2(a1.w);
        __syncthreads();                  // single barrier per chunk

        if (kc < 240) {                   // prefetch next chunk, overlaps compute
            a0 = *(const float4*)(A + (size_t)(m0 + lm) * 256 + kc + 16 + lh);
            a1 = *(const float4*)(A + (size_t)(m0 + lm) * 256 + kc + 16 + lh + 4);
        }

        const unsigned long long* adr = ad + ty * 8;
        const float* wr = Ws + (size_t)kc * 68 + tx * 4;
#pragma unroll
        for (int kk = 0; kk < 16; kk++) {
            ulonglong2 am0 = *(const ulonglong2*)(adr + kk * 130);
            ulonglong2 am1 = *(const ulonglong2*)(adr + kk * 130 + 2);
            ulonglong2 am2 = *(const ulonglong2*)(adr + kk * 130 + 4);
            ulonglong2 am3 = *(const ulonglong2*)(adr + kk * 130 + 6);
            ulonglong2 wp  = *(const ulonglong2*)(wr + kk * 68);
            ffma2(acc[0][0], am0.x, wp.x); ffma2(acc[0][1], am0.x, wp.y);
            ffma2(acc[1][0], am0.y, wp.x); ffma2(acc[1][1], am0.y, wp.y);
            ffma2(acc[2][0], am1.x, wp.x); ffma2(acc[2][1], am1.x, wp.y);
            ffma2(acc[3][0], am1.y, wp.x); ffma2(acc[3][1], am1.y, wp.y);
            ffma2(acc[4][0], am2.x, wp.x); ffma2(acc[4][1], am2.x, wp.y);
            ffma2(acc[5][0], am2.y, wp.x); ffma2(acc[5][1], am2.y, wp.y);
            ffma2(acc[6][0], am3.x, wp.x); ffma2(acc[6][1], am3.x, wp.y);
            ffma2(acc[7][0], am3.y, wp.x); ffma2(acc[7][1], am3.y, wp.y);
        }
        buf ^= 1;
    }

    float C[8][4];
#pragma unroll
    for (int i = 0; i < 8; i++) {
        unpack2(C[i][0], C[i][1], acc[i][0]);
        unpack2(C[i][2], C[i][3], acc[i][1]);
    }

    if (mode == 2) {
        // bias per ROW (output dim); transposed store into [b][h][d][t]
        int n = n0 + tx * 4;                  // token base (4 consecutive)
        int bb = n >> 13, t = n & (T_ - 1);
#pragma unroll
        for (int i = 0; i < 8; i++) {
            int r = m0 + ty * 8 + i;          // output dim 0..255
            float br = bias[r];
            int h = r >> 5, d = r & 31;
            float* cp = C0 + (((size_t)((bb * H_ + h) * HD_ + d)) << 13) + t;
            *(float4*)cp = make_float4(C[i][0] + br, C[i][1] + br,
                                       C[i][2] + br, C[i][3] + br);
        }
        return;
    }

    int n = n0 + tx * 4;
    float4 bj = *(const float4*)(bias + n);
    if (mode == 0) {
#pragma unroll
        for (int i = 0; i < 8; i++) {
            float* cp = C0 + (size_t)(m0 + ty * 8 + i) * DIM_ + n;
            *(float4*)cp = make_float4(C[i][0] + bj.x, C[i][1] + bj.y,
                                       C[i][2] + bj.z, C[i][3] + bj.w);
        }
    } else {
        // mode 1: V head-major [b][h][t][d]
        int h = n >> 5, d = n & 31;
#pragma unroll
        for (int i = 0; i < 8; i++) {
            int m = m0 + ty * 8 + i;
            int b = m >> 13, t = m & (T_ - 1);
            float* cp = C0 + ((size_t)((b * H_ + h) * T_ + t)) * HD_ + d;
            *(float4*)cp = make_float4(C[i][0] + bj.x, C[i][1] + bj.y,
                                       C[i][2] + bj.z, C[i][3] + bj.w);
        }
    }
}

// ---------------------------------------------------------------------------
// Flash attention, fp32 + f32x2, dup-Q in smem, 3 CTAs/SM, 2 barriers/chunk.
// Grid (Lq/64, H, B), 256 threads: tx = tid&15 (4 keys), ty = tid>>4 (4 queries).
// QK: acc[q][kpair] += dupQ[d][q] * Kpair[d][k]   (Q broadcast, K conflict-free)
// PV: oacc[qpair][d] += Ppair[k][q] * dupV        (V double-buffered in smem)
// Dynamic smem: Qs2 16384 + Ks 8704 + V 2*8192 + Pt 17408 = 58880 B.
// ---------------------------------------------------------------------------
#define ATTN_SMEM (16384 + 8704 + 2 * 8192 + 17408)

__global__ __launch_bounds__(256, 3) void attn_kernel()
{
    extern __shared__ char smraw[];
    unsigned long long* Qs2 = (unsigned long long*)smraw;          // [32][64] dup
    float* Ks = (float*)(smraw + 16384);                           // [32][68]
    float* Vb = (float*)(smraw + 16384 + 8704);                    // [2][64][32]
    float* Pt = (float*)(smraw + 16384 + 8704 + 16384);            // [64][68]

    const int tid = threadIdx.x;
    const int tx = tid & 15;
    const int ty = tid >> 4;
    const int qb = blockIdx.x;
    const int h  = blockIdx.y;
    const int b  = blockIdx.z;
    const int qg0 = qb << 6;

    const float scale = 0.17677669529663688f;   // 1/sqrt(32)

    const float* Ktg = g_K + (size_t)(b * H_ + h) * HD_ * T_;      // [d][t]
    const float4* Vtg4 = (const float4*)(g_V + (size_t)(b * H_ + h) * T_ * HD_);

    // ---- Qs2[d][q] = dup2(Q * scale), once per CTA ----
#pragma unroll
    for (int r = 0; r < 2; r++) {
        int i = tid + (r << 8);          // 0..511
        int q = i >> 3, c4 = i & 7;
        float4 v = *(const float4*)(g_Q + ((size_t)(b * LQ_ + qg0 + q) * DIM_ + h * HD_ + c4 * 4));
        Qs2[(4 * c4 + 0) * 64 + q] = dup2(v.x * scale);
        Qs2[(4 * c4 + 1) * 64 + q] = dup2(v.y * scale);
        Qs2[(4 * c4 + 2) * 64 + q] = dup2(v.z * scale);
        Qs2[(4 * c4 + 3) * 64 + q] = dup2(v.w * scale);
    }

    unsigned long long oacc[2][2];      // [q-pair][dim]
    oacc[0][0] = oacc[0][1] = oacc[1][0] = oacc[1][1] = 0ull;
    float mreg[4], lreg[4];
#pragma unroll
    for (int i = 0; i < 4; i++) { mreg[i] = -1e30f; lreg[i] = 0.f; }

    const int dK = tid >> 4;            // 0..15 (+16 second half)
    const int cK = tid & 15;

    const float* mrow0 = g_mask + (size_t)(qg0 + 4 * ty + 0) * T_;
    const float* mrow1 = mrow0 + T_;
    const float* mrow2 = mrow1 + T_;
    const float* mrow3 = mrow2 + T_;

    // preload chunk 0
    float4 kreg[2], vreg[2];
#pragma unroll
    for (int r = 0; r < 2; r++) {
        kreg[r] = *(const float4*)(Ktg + (size_t)(dK + r * 16) * T_ + cK * 4);
        vreg[r] = Vtg4[tid + r * 256];
    }

    int buf = 0;
    for (int t0 = 0; t0 < T_; t0 += 64) {
        // ---- commit prefetched K (single buf) and V (double buf) ----
        float* Vcur = Vb + buf * 2048;
#pragma unroll
        for (int r = 0; r < 2; r++) {
            *(float4*)&Ks[(dK + r * 16) * 68 + cK * 4] = kreg[r];
            ((float4*)Vcur)[tid + r * 256] = vreg[r];
        }
        __syncthreads();   // commit visible; also orders prev-PV before this publish

        if (t0 + 64 < T_) {
#pragma unroll
            for (int r = 0; r < 2; r++) {
                kreg[r] = *(const float4*)(Ktg + (size_t)(dK + r * 16) * T_ + (t0 + 64) + cK * 4);
                vreg[r] = Vtg4[(t0 + 64) * 8 + tid + r * 256];
            }
        }

        // packed mask pairs for 4q x 4k (k-packed, matches accumulator packing)
        ulonglong2 mk0 = *(const ulonglong2*)(mrow0 + t0 + 4 * tx);
        ulonglong2 mk1 = *(const ulonglong2*)(mrow1 + t0 + 4 * tx);
        ulonglong2 mk2 = *(const ulonglong2*)(mrow2 + t0 + 4 * tx);
        ulonglong2 mk3 = *(const ulonglong2*)(mrow3 + t0 + 4 * tx);

        // ---- QK: acc[i][kp], q = 4ty+i, keys 4tx+2kp,+1 ----
        unsigned long long acc[4][2];
#pragma unroll
        for (int i = 0; i < 4; i++) { acc[i][0] = 0ull; acc[i][1] = 0ull; }

        const unsigned long long* qcol = Qs2 + 4 * ty;
        const float* kcol = Ks + 4 * tx;
#pragma unroll
        for (int d = 0; d < 32; d++) {
            ulonglong2 qd0 = *(const ulonglong2*)(qcol + d * 64);      // dup q0,q1
            ulonglong2 qd1 = *(const ulonglong2*)(qcol + d * 64 + 2);  // dup q2,q3
            ulonglong2 kv  = *(const ulonglong2*)(kcol + d * 68);      // k pairs
            ffma2(acc[0][0], qd0.x, kv.x); ffma2(acc[0][1], qd0.x, kv.y);
            ffma2(acc[1][0], qd0.y, kv.x); ffma2(acc[1][1], qd0.y, kv.y);
            ffma2(acc[2][0], qd1.x, kv.x); ffma2(acc[2][1], qd1.x, kv.y);
            ffma2(acc[3][0], qd1.y, kv.x); ffma2(acc[3][1], qd1.y, kv.y);
        }
        // packed mask add
        acc[0][0] = fadd2(acc[0][0], mk0.x); acc[0][1] = fadd2(acc[0][1], mk0.y);
        acc[1][0] = fadd2(acc[1][0], mk1.x); acc[1][1] = fadd2(acc[1][1], mk1.y);
        acc[2][0] = fadd2(acc[2][0], mk2.x); acc[2][1] = fadd2(acc[2][1], mk2.y);
        acc[3][0] = fadd2(acc[3][0], mk3.x); acc[3][1] = fadd2(acc[3][1], mk3.y);

        float s[4][4];
#pragma unroll
        for (int i = 0; i < 4; i++) {
            unpack2(s[i][0], s[i][1], acc[i][0]);
            unpack2(s[i][2], s[i][3], acc[i][1]);
        }

        // ---- online softmax (per q row; reduce across 16 tx lanes) ----
        float alpha[4];
#pragma unroll
        for (int i = 0; i < 4; i++) {
            float rm = fmaxf(fmaxf(s[i][0], s[i][1]), fmaxf(s[i][2], s[i][3]));
            rm = fmaxf(rm, __shfl_xor_sync(0xffffffffu, rm, 1));
            rm = fmaxf(rm, __shfl_xor_sync(0xffffffffu, rm, 2));
            rm = fmaxf(rm, __shfl_xor_sync(0xffffffffu, rm, 4));
            rm = fmaxf(rm, __shfl_xor_sync(0xffffffffu, rm, 8));
            float nm = fmaxf(mreg[i], rm);
            float al = __expf(mreg[i] - nm);
            mreg[i] = nm;
            float rs = 0.f;
#pragma unroll
            for (int k = 0; k < 4; k++) {
                float p = __expf(s[i][k] - nm);
                s[i][k] = p;
                rs += p;
            }
            rs += __shfl_xor_sync(0xffffffffu, rs, 1);
            rs += __shfl_xor_sync(0xffffffffu, rs, 2);
            rs += __shfl_xor_sync(0xffffffffu, rs, 4);
            rs += __shfl_xor_sync(0xffffffffu, rs, 8);
            lreg[i] = lreg[i] * al + rs;
            alpha[i] = al;
        }
        {
            unsigned long long ap0 = pack2(alpha[0], alpha[1]);
            unsigned long long ap1 = pack2(alpha[2], alpha[3]);
            fmul2(oacc[0][0], ap0); fmul2(oacc[0][1], ap0);
            fmul2(oacc[1][0], ap1); fmul2(oacc[1][1], ap1);
        }

        // ---- publish P (q-consecutive, swizzled column groups) ----
#pragma unroll
        for (int kk = 0; kk < 4; kk++) {
            int k = 4 * tx + kk;
            int cg = (ty + tx) & 15;     // (ty + (k>>2)) & 15
            *(float4*)&Pt[k * 68 + 4 * cg] =
                make_float4(s[0][kk], s[1][kk], s[2][kk], s[3][kk]);
        }
        __syncthreads();

        // ---- PV over 64 keys: V from current buffer ----
        {
            const float* vp = Vcur + 2 * tx;
#pragma unroll 8
            for (int k = 0; k < 64; k++) {
                int cg = (ty + (k >> 2)) & 15;
                ulonglong2 pp = *(const ulonglong2*)&Pt[k * 68 + 4 * cg];
                float2 vv = *(const float2*)(vp + k * 32);
                unsigned long long v0 = dup2(vv.x), v1 = dup2(vv.y);
                ffma2(oacc[0][0], pp.x, v0); ffma2(oacc[0][1], pp.x, v1);
                ffma2(oacc[1][0], pp.y, v0); ffma2(oacc[1][1], pp.y, v1);
            }
        }
        buf ^= 1;
        // NOTE: no third barrier. Next iter's K commit is safe (all warps passed
        // this chunk's mid-barrier => finished QK); V commit targets other buffer;
        // Pt re-publish happens only after next iter's top barrier.
    }

    // ---- finalize ----
    float of[4][2];
    unpack2(of[0][0], of[1][0], oacc[0][0]);
    unpack2(of[0][1], of[1][1], oacc[0][1]);
    unpack2(of[2][0], of[3][0], oacc[1][0]);
    unpack2(of[2][1], of[3][1], oacc[1][1]);

    float* ob = g_att + (size_t)(b * LQ_ + qg0 + 4 * ty) * DIM_ + h * HD_ + 2 * tx;
#pragma unroll
    for (int i = 0; i < 4; i++) {
        float inv = 1.0f / lreg[i];
        *(float2*)(ob + (size_t)i * DIM_) = make_float2(of[i][0] * inv, of[i][1] * inv);
    }
}

// ---------------------------------------------------------------------------
// Launch
// ---------------------------------------------------------------------------
extern "C" void kernel_launch(void* const* d_in, const int* in_sizes, int n_in,
                              void* d_out, int out_size)
{
    const float* q_in       = (const float*)d_in[0];   // [8,512,256]
    const float* kv_in      = (const float*)d_in[1];   // [8,8192,256]
    const float* w_in       = (const float*)d_in[2];   // [768,256]
    const float* b_in       = (const float*)d_in[3];   // [768]
    const float* w_out      = (const float*)d_in[4];   // [256,256]
    const float* b_out      = (const float*)d_in[5];   // [256]
    const float* rel_bias   = (const float*)d_in[6];   // [257]
    const float* mask_scale = (const float*)d_in[7];   // [1]
    float* out = (float*)d_out;                        // [8,512,256]

    float *gQ, *gK, *gV, *gAtt;
    cudaGetSymbolAddress((void**)&gQ,   g_Q);
    cudaGetSymbolAddress((void**)&gK,   g_K);
    cudaGetSymbolAddress((void**)&gV,   g_V);
    cudaGetSymbolAddress((void**)&gAtt, g_att);

    cudaFuncSetAttribute(gemm_rw, cudaFuncAttributeMaxDynamicSharedMemorySize, GEMM_SMEM);
    cudaFuncSetAttribute(attn_kernel, cudaFuncAttributeMaxDynamicSharedMemorySize, ATTN_SMEM);

    // 1. mask precompute [512,8192]
    mask_kernel<<<(LQ_ * T_) / 256, 256>>>(rel_bias, mask_scale);

    // 2. Q projection: [4096,256] @ wq^T -> g_Q row-major
    gemm_rw<<<dim3(4, 32), 256, GEMM_SMEM>>>(q_in, w_in, b_in, gQ, 0);

    // 3. V projection: [65536,256] @ wv^T -> g_V head-major [b][h][t][d]
    gemm_rw<<<dim3(4, 512), 256, GEMM_SMEM>>>(kv_in, w_in + 2 * 256 * 256, b_in + 512, gV, 1);

    // 4. K projection, transposed orientation: C[dim][token] -> g_K [b][h][d][t]
    gemm_rw<<<dim3(1024, 2), 256, GEMM_SMEM>>>(w_in + 256 * 256, kv_in, b_in + 256, gK, 2);

    // 5. attention
    attn_kernel<<<dim3(LQ_ / 64, H_, B_), 256, ATTN_SMEM>>>();

    // 6. output projection
    gemm_rw<<<dim3(4, 32), 256, GEMM_SMEM>>>(gAtt, w_out, b_out, out, 0);
}